// round 1
// baseline (speedup 1.0000x reference)
#include <cuda_runtime.h>

#define NN 10000
#define NE 320000
#define F_IN 128
#define F_HID 256

// ---------------- scratch (device globals; no allocation allowed) ----------------
__device__ int   g_deg[NN];          // out-degree (by src)
__device__ int   g_incnt[NN];        // in-degree  (by dst)
__device__ int   g_roff[NN + 1];     // CSR row offsets (by dst)
__device__ int   g_cursor[NN];       // fill cursors
__device__ float g_inv[NN];          // 1/out-degree
__device__ int   g_csr_src[NE];
__device__ float g_csr_w[NE];
__device__ float g_bufA[NN * F_HID];
__device__ float g_bufB[NN * F_HID];
__device__ float g_vsum;

// ---------------- graph preprocessing ----------------
__global__ void zero_kernel() {
    int i = blockIdx.x * blockDim.x + threadIdx.x;
    if (i < NN) { g_deg[i] = 0; g_incnt[i] = 0; }
    if (i == 0) g_vsum = 0.0f;
}

__global__ void count_kernel(const int* __restrict__ src, const int* __restrict__ dst) {
    int e = blockIdx.x * blockDim.x + threadIdx.x;
    if (e < NE) {
        atomicAdd(&g_deg[src[e]], 1);
        atomicAdd(&g_incnt[dst[e]], 1);
    }
}

// single-block exclusive scan over in-degree counts -> row offsets + cursors + inv-deg
__global__ void scan_kernel() {
    __shared__ int carry;
    __shared__ int wsum[32];
    int tid = threadIdx.x;  // 1024 threads
    if (tid == 0) carry = 0;
    __syncthreads();
    for (int base = 0; base < NN; base += 1024) {
        int i = base + tid;
        int v = (i < NN) ? g_incnt[i] : 0;
        int x = v;
        #pragma unroll
        for (int o = 1; o < 32; o <<= 1) {
            int y = __shfl_up_sync(0xffffffffu, x, o);
            if ((tid & 31) >= o) x += y;
        }
        if ((tid & 31) == 31) wsum[tid >> 5] = x;
        __syncthreads();
        if (tid < 32) {
            int s = wsum[tid];
            int t = s;
            #pragma unroll
            for (int o = 1; o < 32; o <<= 1) {
                int y = __shfl_up_sync(0xffffffffu, t, o);
                if (tid >= o) t += y;
            }
            wsum[tid] = t - s;  // exclusive warp offset
        }
        __syncthreads();
        int incl = x + wsum[tid >> 5] + carry;
        if (i < NN) { g_roff[i + 1] = incl; g_cursor[i] = incl - v; }
        __syncthreads();
        if (tid == 1023) carry = incl;
        __syncthreads();
    }
    if (tid == 0) g_roff[0] = 0;
    for (int i = tid; i < NN; i += 1024) {
        int d = g_deg[i];
        g_inv[i] = (d > 0) ? 1.0f / (float)d : 0.0f;
    }
}

__global__ void fill_kernel(const int* __restrict__ src, const int* __restrict__ dst) {
    int e = blockIdx.x * blockDim.x + threadIdx.x;
    if (e < NE) {
        int d = dst[e];
        int p = atomicAdd(&g_cursor[d], 1);
        int s = src[e];
        g_csr_src[p] = s;
        g_csr_w[p]   = g_inv[s];
    }
}

// ---------------- edge aggregation: Y[d] = sum_{e: dst=d} w_e * X[src_e] ----------------
// warp per node; lane owns CHUNKS float4 feature slices (CHUNKS=1 -> F=128, 2 -> F=256)
template <int CHUNKS>
__global__ void aggregate_kernel(const float* __restrict__ X, float* __restrict__ Y, int F) {
    int gw    = (blockIdx.x * blockDim.x + threadIdx.x) >> 5;
    int lane  = threadIdx.x & 31;
    int nwrp  = (gridDim.x * blockDim.x) >> 5;
    for (int n = gw; n < NN; n += nwrp) {
        int s0 = g_roff[n], s1 = g_roff[n + 1];
        float4 acc0 = make_float4(0.f, 0.f, 0.f, 0.f);
        float4 acc1 = make_float4(0.f, 0.f, 0.f, 0.f);
        for (int e0 = s0; e0 < s1; e0 += 32) {
            int e = e0 + lane;
            int   ss = 0; float ww = 0.f;
            if (e < s1) { ss = g_csr_src[e]; ww = g_csr_w[e]; }
            int cnt = min(32, s1 - e0);
            for (int j = 0; j < cnt; j++) {
                int   sj = __shfl_sync(0xffffffffu, ss, j);
                float wj = __shfl_sync(0xffffffffu, ww, j);
                const float4* xp = (const float4*)(X + (size_t)sj * F);
                float4 v0 = xp[lane];
                acc0.x += wj * v0.x; acc0.y += wj * v0.y;
                acc0.z += wj * v0.z; acc0.w += wj * v0.w;
                if (CHUNKS == 2) {
                    float4 v1 = xp[lane + 32];
                    acc1.x += wj * v1.x; acc1.y += wj * v1.y;
                    acc1.z += wj * v1.z; acc1.w += wj * v1.w;
                }
            }
        }
        float4* yp = (float4*)(Y + (size_t)n * F);
        yp[lane] = acc0;
        if (CHUNKS == 2) yp[lane + 32] = acc1;
    }
}

// ---------------- C = act(A[M,K] @ W[K,256] + b), C row stride 256 ----------------
// 64x64 block tile, 256 threads, 4x4 micro-tile, BK=16
__global__ void gemm_bias_act(const float* __restrict__ A, const float* __restrict__ W,
                              const float* __restrict__ bias, float* __restrict__ C,
                              int M, int K, int relu) {
    __shared__ float As[16][68];   // [k][m], padded (68*4B keeps 16B alignment per row)
    __shared__ float Bs[16][64];   // [k][n]
    int tid = threadIdx.x;
    int bm0 = blockIdx.x * 64;
    int bn0 = blockIdx.y * 64;
    int tx = tid & 15, ty = tid >> 4;

    int arow = tid >> 2;           // 0..63
    int acol = (tid & 3) * 4;      // 0,4,8,12
    int brow = tid >> 4;           // 0..15
    int bcol = (tid & 15) * 4;     // 0..60

    float acc[4][4] = {};

    for (int k0 = 0; k0 < K; k0 += 16) {
        float4 av = make_float4(0.f, 0.f, 0.f, 0.f);
        if (bm0 + arow < M)
            av = *(const float4*)(A + (size_t)(bm0 + arow) * K + k0 + acol);
        As[acol + 0][arow] = av.x;
        As[acol + 1][arow] = av.y;
        As[acol + 2][arow] = av.z;
        As[acol + 3][arow] = av.w;
        float4 bv = *(const float4*)(W + (size_t)(k0 + brow) * 256 + bn0 + bcol);
        *(float4*)&Bs[brow][bcol] = bv;
        __syncthreads();
        #pragma unroll
        for (int kk = 0; kk < 16; kk++) {
            float4 a = *(float4*)&As[kk][ty * 4];
            float4 b = *(float4*)&Bs[kk][tx * 4];
            float ar[4] = {a.x, a.y, a.z, a.w};
            float br[4] = {b.x, b.y, b.z, b.w};
            #pragma unroll
            for (int i = 0; i < 4; i++)
                #pragma unroll
                for (int j = 0; j < 4; j++)
                    acc[i][j] += ar[i] * br[j];
        }
        __syncthreads();
    }

    #pragma unroll
    for (int i = 0; i < 4; i++) {
        int r = bm0 + ty * 4 + i;
        if (r < M) {
            #pragma unroll
            for (int j = 0; j < 4; j++) {
                int c = bn0 + tx * 4 + j;
                float v = acc[i][j] + bias[c];
                if (relu) v = fmaxf(v, 0.f);
                C[(size_t)r * 256 + c] = v;
            }
        }
    }
}

// ---------------- heads: PI[n] = h3[n].Wp + bp ; vsum += h3[n].Wv ----------------
__global__ void heads_kernel(const float* __restrict__ H, const float* __restrict__ Wp,
                             const float* __restrict__ bp, const float* __restrict__ Wv,
                             float* __restrict__ out) {
    int gw   = (blockIdx.x * blockDim.x + threadIdx.x) >> 5;
    int lane = threadIdx.x & 31;
    int nwrp = (gridDim.x * blockDim.x) >> 5;
    const float4* p4 = (const float4*)Wp;
    const float4* v4 = (const float4*)Wv;
    for (int n = gw; n < NN; n += nwrp) {
        const float4* h4 = (const float4*)(H + (size_t)n * 256);
        float4 h0 = h4[lane], h1 = h4[lane + 32];
        float4 a0 = p4[lane], a1 = p4[lane + 32];
        float4 b0 = v4[lane], b1 = v4[lane + 32];
        float dp = h0.x * a0.x + h0.y * a0.y + h0.z * a0.z + h0.w * a0.w
                 + h1.x * a1.x + h1.y * a1.y + h1.z * a1.z + h1.w * a1.w;
        float dv = h0.x * b0.x + h0.y * b0.y + h0.z * b0.z + h0.w * b0.w
                 + h1.x * b1.x + h1.y * b1.y + h1.z * b1.z + h1.w * b1.w;
        #pragma unroll
        for (int o = 16; o > 0; o >>= 1) {
            dp += __shfl_xor_sync(0xffffffffu, dp, o);
            dv += __shfl_xor_sync(0xffffffffu, dv, o);
        }
        if (lane == 0) {
            out[n] = dp + bp[0];
            atomicAdd(&g_vsum, dv);
        }
    }
}

__global__ void final_kernel(const float* __restrict__ bv, float* __restrict__ out) {
    if (threadIdx.x == 0)
        out[NN] = g_vsum * (1.0f / (float)NN) + bv[0];
}

// ---------------- launch ----------------
extern "C" void kernel_launch(void* const* d_in, const int* in_sizes, int n_in,
                              void* d_out, int out_size) {
    const float* features = (const float*)d_in[0];
    const int*   src      = (const int*)d_in[1];
    const int*   dst      = (const int*)d_in[2];
    const float* W1 = (const float*)d_in[3];
    const float* b1 = (const float*)d_in[4];
    const float* W2 = (const float*)d_in[5];
    const float* b2 = (const float*)d_in[6];
    const float* W3 = (const float*)d_in[7];
    const float* b3 = (const float*)d_in[8];
    const float* Wp = (const float*)d_in[9];
    const float* bp = (const float*)d_in[10];
    const float* Wv = (const float*)d_in[11];
    const float* bv = (const float*)d_in[12];
    float* out = (float*)d_out;

    void *pA_, *pB_;
    cudaGetSymbolAddress(&pA_, g_bufA);
    cudaGetSymbolAddress(&pB_, g_bufB);
    float* bufA = (float*)pA_;
    float* bufB = (float*)pB_;

    // graph preprocessing (CSR by dst, left-normalization weights)
    zero_kernel<<<(NN + 255) / 256, 256>>>();
    count_kernel<<<(NE + 255) / 256, 256>>>(src, dst);
    scan_kernel<<<1, 1024>>>();
    fill_kernel<<<(NE + 255) / 256, 256>>>(src, dst);

    dim3 ggrid((NN + 63) / 64, 4);

    // layer 1: aggregate(features) [N,128] -> GEMM W1 + relu -> [N,256]
    aggregate_kernel<1><<<1250, 256>>>(features, bufA, 128);
    gemm_bias_act<<<ggrid, 256>>>(bufA, W1, b1, bufB, NN, 128, 1);
    // layer 2
    aggregate_kernel<2><<<1250, 256>>>(bufB, bufA, 256);
    gemm_bias_act<<<ggrid, 256>>>(bufA, W2, b2, bufB, NN, 256, 1);
    // layer 3 (no activation)
    aggregate_kernel<2><<<1250, 256>>>(bufB, bufA, 256);
    gemm_bias_act<<<ggrid, 256>>>(bufA, W3, b3, bufB, NN, 256, 0);

    // heads
    heads_kernel<<<1250, 256>>>(bufB, Wp, bp, Wv, out);
    final_kernel<<<1, 32>>>(bv, out);
}